// round 4
// baseline (speedup 1.0000x reference)
#include <cuda_runtime.h>
#include <cuda_bf16.h>
#include <math.h>

#define NTOT 4096
#define Q 1024
#define LDA 1024
#define NB 64

// A is Q+1 rows x Q cols: rows 0..1023 = S, row 1024 = border vector v (becomes w = L^-1 v)
__device__ __align__(128) float g_A[(Q + 1) * LDA];
__device__ float  g_u[Q];
__device__ int    g_cnt[Q];
__device__ float  g_sw[Q];
__device__ double g_sumrr;
__device__ double g_uDu;
__device__ double g_logdet;

// ---------------- setup kernels ----------------

__global__ void init_kernel() {
    int i = blockIdx.x * blockDim.x + threadIdx.x;
    if (i < Q) { g_u[i] = 0.f; g_cnt[i] = 0; }
    if (i == 0) { g_sumrr = 0.0; g_uDu = 0.0; g_logdet = 0.0; }
}

// Z_idx arrives as int32 (JAX x64-disabled downcasts the reference's int64).
__global__ void scatter_kernel(const float* __restrict__ yt,
                               const float* __restrict__ yp,
                               const int* __restrict__ Z) {
    int i = blockIdx.x * blockDim.x + threadIdx.x;
    float r2 = 0.f;
    if (i < NTOT) {
        float r = yt[i] - yp[i];
        int q = Z[i] & (Q - 1);   // defensive: keep atomic in-bounds
        atomicAdd(&g_u[q], r);
        atomicAdd(&g_cnt[q], 1);
        r2 = r * r;
    }
    #pragma unroll
    for (int o = 16; o > 0; o >>= 1) r2 += __shfl_down_sync(0xffffffffu, r2, o);
    if ((threadIdx.x & 31) == 0) atomicAdd(&g_sumrr, (double)r2);
}

__global__ void sw_kernel() {
    int i = blockIdx.x * blockDim.x + threadIdx.x;
    if (i < Q) g_sw[i] = sqrtf((float)g_cnt[i]);
}

// One block per row i: builds S row, computes (D u)_i, v_i, and uDu contribution.
__global__ void build_kernel(const float* __restrict__ dist,
                             const float* __restrict__ sig2e_p,
                             const float* __restrict__ sig2bs) {
    int i = blockIdx.x;
    float s0   = sig2bs[0];
    float cexp = -0.5f / sig2bs[1];
    float se   = *sig2e_p;
    float swi  = g_sw[i];
    float partial = 0.f;
    const float* drow = dist + (size_t)i * Q;
    for (int j = threadIdx.x; j < Q; j += 256) {
        float e = s0 * __expf(cexp * drow[j]);
        float v = swi * g_sw[j] * e;
        if (j == i) v += se;
        g_A[(size_t)i * LDA + j] = v;
        partial += e * g_u[j];
    }
    __shared__ float red[256];
    red[threadIdx.x] = partial;
    __syncthreads();
    for (int s = 128; s > 0; s >>= 1) {
        if (threadIdx.x < s) red[threadIdx.x] += red[threadIdx.x + s];
        __syncthreads();
    }
    if (threadIdx.x == 0) {
        float dot = red[0];
        g_A[(size_t)Q * LDA + i] = swi * dot;   // border row v
        atomicAdd(&g_uDu, (double)(g_u[i] * dot));
    }
}

// ---------------- Cholesky: panel factor (NB x NB diag block) ----------------
// blockDim = (64, 4). Thread (r, cg) owns row r, column-stripe cg (stride 4).
__global__ void factor_kernel(int j0) {
    __shared__ float s[NB][NB + 1];
    __shared__ float col[NB];
    __shared__ float shinv;
    __shared__ double dred[NB];
    int r  = threadIdx.x;
    int cg = threadIdx.y;
    for (int c = cg; c < NB; c += 4)
        s[r][c] = g_A[(size_t)(j0 + r) * LDA + j0 + c];
    __syncthreads();
    double lg = 0.0;
    for (int j = 0; j < NB; j++) {
        if (r == j && cg == 0) {
            float d = sqrtf(s[j][j]);
            s[j][j] = d;
            shinv = 1.0f / d;
            lg += log((double)d);
        }
        __syncthreads();
        if (cg == 0 && r > j) col[r] = s[r][j] * shinv;
        __syncthreads();
        if (r > j) {
            float lrj = col[r];
            if (cg == 0) s[r][j] = lrj;
            for (int k = j + 1 + cg; k <= r; k += 4)
                s[r][k] -= lrj * col[k];
        }
    }
    __syncthreads();
    for (int c = cg; c < NB; c += 4)
        g_A[(size_t)(j0 + r) * LDA + j0 + c] = s[r][c];
    if (cg == 0) dred[r] = lg;
    __syncthreads();
    if (r == 0 && cg == 0) {
        double t = 0.0;
        for (int i = 0; i < NB; i++) t += dred[i];
        atomicAdd(&g_logdet, t);
    }
}

// ---------------- Cholesky: TRSM (warp per row, shuffle chain) ----------------
__global__ void trsm_kernel(int j0) {
    __shared__ float sL[NB * (NB + 1)];
    __shared__ float sinv[NB];
    int tid = threadIdx.x;
    for (int idx = tid; idx < NB * NB; idx += 256) {
        int rr = idx >> 6, cc = idx & 63;
        sL[rr * (NB + 1) + cc] = g_A[(size_t)(j0 + rr) * LDA + j0 + cc];
    }
    __syncthreads();
    if (tid < NB) sinv[tid] = 1.0f / sL[tid * (NB + 1) + tid];
    __syncthreads();
    int gw   = blockIdx.x * 8 + (tid >> 5);
    int lane = tid & 31;
    int i = j0 + NB + gw;
    if (i > Q) return;
    float a0 = g_A[(size_t)i * LDA + j0 + lane];
    float a1 = g_A[(size_t)i * LDA + j0 + 32 + lane];
    #pragma unroll
    for (int m = 0; m < NB; m++) {
        float xs = ((m < 32) ? a0 : a1) * sinv[m];
        float x  = __shfl_sync(0xffffffffu, xs, m & 31);
        if (m < 32) {
            if (lane == m)      a0 = x;
            else if (lane > m)  a0 -= x * sL[lane * (NB + 1) + m];
            a1 -= x * sL[(lane + 32) * (NB + 1) + m];
        } else {
            if (lane == m - 32)     a1 = x;
            else if (lane > m - 32) a1 -= x * sL[(lane + 32) * (NB + 1) + m];
        }
    }
    g_A[(size_t)i * LDA + j0 + lane]      = a0;
    g_A[(size_t)i * LDA + j0 + 32 + lane] = a1;
}

// ---------------- Cholesky: SYRK trailing update (64x64 tiles) ----------------
__global__ void syrk_kernel(int j0) {
    int jb = j0 + NB;
    int r0 = jb + blockIdx.y * 64;
    int c0 = jb + blockIdx.x * 64;
    if (c0 > r0) return;   // uniform per-block: skip strictly-upper tiles
    __shared__ float As[64][65];
    __shared__ float Bs[64][65];
    int tid = threadIdx.x;
    for (int idx = tid; idx < 64 * 16; idx += 256) {
        int rr = idx >> 4, c4 = (idx & 15) * 4;
        int gi = r0 + rr;
        float4 va = (gi <= Q) ? *(const float4*)&g_A[(size_t)gi * LDA + j0 + c4]
                              : make_float4(0.f, 0.f, 0.f, 0.f);
        As[rr][c4 + 0] = va.x; As[rr][c4 + 1] = va.y;
        As[rr][c4 + 2] = va.z; As[rr][c4 + 3] = va.w;
        float4 vb = *(const float4*)&g_A[(size_t)(c0 + rr) * LDA + j0 + c4];
        Bs[rr][c4 + 0] = vb.x; Bs[rr][c4 + 1] = vb.y;
        Bs[rr][c4 + 2] = vb.z; Bs[rr][c4 + 3] = vb.w;
    }
    __syncthreads();
    int tx = tid & 15, ty = tid >> 4;
    float acc[4][4] = {};
    #pragma unroll
    for (int kk = 0; kk < 64; kk++) {
        float a[4], b[4];
        #pragma unroll
        for (int p = 0; p < 4; p++) { a[p] = As[ty * 4 + p][kk]; b[p] = Bs[tx * 4 + p][kk]; }
        #pragma unroll
        for (int p = 0; p < 4; p++)
            #pragma unroll
            for (int q = 0; q < 4; q++)
                acc[p][q] += a[p] * b[q];
    }
    #pragma unroll
    for (int p = 0; p < 4; p++) {
        int i = r0 + ty * 4 + p;
        if (i > Q) continue;
        #pragma unroll
        for (int q = 0; q < 4; q++) {
            int k = c0 + tx * 4 + q;
            g_A[(size_t)i * LDA + k] -= acc[p][q];
        }
    }
}

// ---------------- final reduction ----------------
__global__ void final_kernel(const float* __restrict__ sig2e_p, float* __restrict__ out) {
    __shared__ double red[256];
    double t = 0.0;
    for (int j = threadIdx.x; j < Q; j += 256) {
        float w = g_A[(size_t)Q * LDA + j];
        t += (double)w * (double)w;
    }
    red[threadIdx.x] = t;
    __syncthreads();
    for (int s = 128; s > 0; s >>= 1) {
        if (threadIdx.x < s) red[threadIdx.x] += red[threadIdx.x + s];
        __syncthreads();
    }
    if (threadIdx.x == 0) {
        double tt  = red[0];
        double se  = (double)(*sig2e_p);
        double inv = 1.0 / se;
        double quad = inv * g_sumrr - inv * inv * (g_uDu - tt);
        double logdetV = ((double)NTOT - (double)Q) * log(se) + 2.0 * g_logdet;
        const double LOG2PI = 1.8378770664093454835606594728112;
        double loss = 0.5 * (double)NTOT * LOG2PI + 0.5 * logdetV + 0.5 * quad;
        out[0] = (float)loss;
    }
}

extern "C" void kernel_launch(void* const* d_in, const int* in_sizes, int n_in,
                              void* d_out, int out_size) {
    const float* y_true = (const float*)d_in[0];
    const float* y_pred = (const float*)d_in[1];
    const int*   Z_idx  = (const int*)d_in[2];
    const float* dist   = (const float*)d_in[3];
    const float* sig2e  = (const float*)d_in[4];
    const float* sig2bs = (const float*)d_in[5];
    float* out = (float*)d_out;

    init_kernel<<<4, 256>>>();
    scatter_kernel<<<16, 256>>>(y_true, y_pred, Z_idx);
    sw_kernel<<<4, 256>>>();
    build_kernel<<<Q, 256>>>(dist, sig2e, sig2bs);

    for (int p = 0; p < Q / NB; p++) {
        int j0 = p * NB;
        factor_kernel<<<1, dim3(64, 4)>>>(j0);
        int jb = j0 + NB;
        int nrows = (Q + 1) - jb;   // trailing rows incl. border row
        if (nrows > 0) {
            int nblocks = (nrows * 32 + 255) / 256;  // warp per row
            trsm_kernel<<<nblocks, 256>>>(j0);
            int colt = (Q - jb) / 64;
            if (colt > 0) {
                int rowt = (nrows + 63) / 64;
                syrk_kernel<<<dim3(colt, rowt), 256>>>(j0);
            }
        }
    }
    final_kernel<<<1, 256>>>(sig2e, out);
}

// round 5
// speedup vs baseline: 2.6467x; 2.6467x over previous
#include <cuda_runtime.h>
#include <cuda_bf16.h>
#include <math.h>

#define NTOT 4096
#define Q    1024
#define LDA  1024
#define NB   64
#define NBLK 128
#define NTHR 256

// A is (Q+1) x Q: rows 0..1023 = S, row 1024 = border vector v (becomes w = L^-1 v)
__device__ __align__(128) float g_A[(Q + 1) * LDA];
__device__ float  g_u[Q];
__device__ int    g_cnt[Q];
__device__ float  g_sw[Q];
__device__ double g_sumrr;
__device__ double g_uDu;
__device__ double g_logdet;
__device__ unsigned g_barGen = 0;
__device__ unsigned g_barCnt = 0;

__device__ __forceinline__ void grid_barrier() {
    __threadfence();               // make this block's writes visible
    __syncthreads();
    if (threadIdx.x == 0) {
        unsigned gen = *(volatile unsigned*)&g_barGen;
        if (atomicAdd(&g_barCnt, 1u) == NBLK - 1u) {
            g_barCnt = 0;
            __threadfence();
            *(volatile unsigned*)&g_barGen = gen + 1u;
        } else {
            while (*(volatile unsigned*)&g_barGen == gen) { __nanosleep(32); }
        }
    }
    __syncthreads();
    __threadfence();               // acquire side
}

__global__ void __launch_bounds__(NTHR, 1)
mega_kernel(const float* __restrict__ yt,
            const float* __restrict__ yp,
            const int*   __restrict__ Z,
            const float* __restrict__ dist,
            const float* __restrict__ sig2e_p,
            const float* __restrict__ sig2bs,
            float* __restrict__ out)
{
    __shared__ __align__(16) unsigned char shraw[2 * 64 * 65 * 4 + 64 * 8 + 128 * 4];
    float*  shA = (float*)shraw;                       // 64*65 floats
    float*  shB = shA + 64 * 65;                       // 64*65 floats
    double* shD = (double*)(shraw + 2 * 64 * 65 * 4);  // 64 doubles
    float*  shS = (float*)(shD + 64);                  // 128 floats

    const int bid = blockIdx.x;
    const int tid = threadIdx.x;
    const int lane = tid & 31;

    // ---------- phase 0: init ----------
    for (int i = bid * NTHR + tid; i < Q; i += NBLK * NTHR) { g_u[i] = 0.f; g_cnt[i] = 0; }
    if (bid == 0 && tid == 0) { g_sumrr = 0.0; g_uDu = 0.0; g_logdet = 0.0; }
    grid_barrier();

    // ---------- phase 1: scatter (Z arrives as int32) ----------
    {
        int gi = bid * NTHR + tid;
        float r2 = 0.f;
        if (gi < NTOT) {
            float r = yt[gi] - yp[gi];
            int q = Z[gi] & (Q - 1);
            atomicAdd(&g_u[q], r);
            atomicAdd(&g_cnt[q], 1);
            r2 = r * r;
        }
        #pragma unroll
        for (int o = 16; o > 0; o >>= 1) r2 += __shfl_down_sync(0xffffffffu, r2, o);
        if (lane == 0 && (gi - lane) < NTOT) atomicAdd(&g_sumrr, (double)r2);
    }
    grid_barrier();

    // ---------- phase 2: sw ----------
    for (int i = bid * NTHR + tid; i < Q; i += NBLK * NTHR)
        g_sw[i] = sqrtf((float)g_cnt[i]);
    grid_barrier();

    // ---------- phase 3: build S + border v + uDu ----------
    {
        float s0   = sig2bs[0];
        float cexp = -0.5f / sig2bs[1];
        float se   = *sig2e_p;
        double uDu_loc = 0.0;
        for (int i = bid; i < Q; i += NBLK) {
            float swi = g_sw[i];
            float partial = 0.f;
            const float* drow = dist + i * Q;
            for (int j = tid; j < Q; j += NTHR) {
                float e = s0 * __expf(cexp * drow[j]);
                float v = swi * g_sw[j] * e;
                if (j == i) v += se;
                g_A[i * LDA + j] = v;
                partial += e * g_u[j];
            }
            shA[tid] = partial;
            __syncthreads();
            for (int s = 128; s > 0; s >>= 1) {
                if (tid < s) shA[tid] += shA[tid + s];
                __syncthreads();
            }
            if (tid == 0) {
                float dot = shA[0];
                g_A[Q * LDA + i] = swi * dot;
                uDu_loc += (double)(g_u[i] * dot);
            }
            __syncthreads();
        }
        if (tid == 0 && uDu_loc != 0.0) atomicAdd(&g_uDu, uDu_loc);
    }
    grid_barrier();

    // ---------- phase 4: blocked Cholesky of bordered S ----------
    for (int p = 0; p < Q / NB; p++) {
        const int j0 = p * NB;
        const int jb = j0 + NB;

        // ---- factor (block 0 only): 1 barrier per column, deferred scaling ----
        if (bid == 0) {
            float (*s)[65] = (float(*)[65])shA;
            const int r  = tid & 63;
            const int cg = tid >> 6;
            for (int idx = tid; idx < NB * NB; idx += NTHR) {
                int rr = idx >> 6, cc = idx & 63;
                s[rr][cc] = g_A[(j0 + rr) * LDA + j0 + cc];
            }
            __syncthreads();
            for (int j = 0; j < NB; j++) {
                if (tid == j) {                 // own s[j][j] via in-thread RAW
                    float djj = s[j][j];
                    shS[j] = djj;               // raw diag (= d_j^2 of scaled L)
                    shS[64 + (j & 1)] = 1.0f / djj;
                }
                __syncthreads();
                float inv2 = shS[64 + (j & 1)];
                if (r > j) {
                    float t = s[r][j] * inv2;
                    for (int k = j + 1 + cg; k <= r; k += 4)
                        s[r][k] -= t * s[k][j];
                }
            }
            __syncthreads();
            if (tid < NB) {
                float d2 = shS[tid];
                shD[tid] = 0.5 * (double)logf(d2);
                shS[tid] = rsqrtf(d2) ;         // 1/d_j
            }
            __syncthreads();
            if (tid == 0) {
                double t = 0.0;
                #pragma unroll
                for (int i = 0; i < NB; i++) t += shD[i];
                g_logdet += t;                  // single writer, no atomic needed
            }
            // write back L = s * diag(1/d)
            for (int idx = tid; idx < NB * NB; idx += NTHR) {
                int rr = idx >> 6, cc = idx & 63;
                g_A[(j0 + rr) * LDA + j0 + cc] = s[rr][cc] * shS[cc];
            }
        }
        grid_barrier();

        // ---- TRSM: warp per trailing row (incl. border row Q) ----
        {
            float* sL = shA;                    // 64 x 65 flat
            for (int idx = tid; idx < NB * NB; idx += NTHR) {
                int rr = idx >> 6, cc = idx & 63;
                sL[rr * 65 + cc] = g_A[(j0 + rr) * LDA + j0 + cc];
            }
            __syncthreads();
            if (tid < NB) shS[tid] = 1.0f / sL[tid * 65 + tid];
            __syncthreads();
            int i = jb + bid * 8 + (tid >> 5);
            if (i <= Q) {
                float a0 = g_A[i * LDA + j0 + lane];
                float a1 = g_A[i * LDA + j0 + 32 + lane];
                #pragma unroll
                for (int m = 0; m < NB; m++) {
                    float xs = ((m < 32) ? a0 : a1) * shS[m];
                    float x  = __shfl_sync(0xffffffffu, xs, m & 31);
                    if (m < 32) {
                        if (lane == m)      a0 = x;
                        else if (lane > m)  a0 -= x * sL[lane * 65 + m];
                        a1 -= x * sL[(lane + 32) * 65 + m];
                    } else {
                        if (lane == m - 32)     a1 = x;
                        else if (lane > m - 32) a1 -= x * sL[(lane + 32) * 65 + m];
                    }
                }
                g_A[i * LDA + j0 + lane]      = a0;
                g_A[i * LDA + j0 + 32 + lane] = a1;
            }
        }
        grid_barrier();

        // ---- SYRK trailing update: 64x64 tiles, lower-triangular only ----
        {
            int colt = (Q - jb) >> 6;
            if (colt > 0) {
                int rowt = (Q + 1 - jb + 63) >> 6;
                int ntile = rowt * colt;
                float (*As)[65] = (float(*)[65])shA;
                float (*Bs)[65] = (float(*)[65])shB;
                for (int t = bid; t < ntile; t += NBLK) {
                    int ry = t / colt, cx = t - ry * colt;
                    int r0 = jb + ry * 64, c0 = jb + cx * 64;
                    if (c0 <= r0) {
                        for (int idx = tid; idx < 64 * 16; idx += NTHR) {
                            int rr = idx >> 4, c4 = (idx & 15) * 4;
                            int gi = r0 + rr;
                            float4 va = (gi <= Q) ? *(const float4*)&g_A[gi * LDA + j0 + c4]
                                                  : make_float4(0.f, 0.f, 0.f, 0.f);
                            As[rr][c4 + 0] = va.x; As[rr][c4 + 1] = va.y;
                            As[rr][c4 + 2] = va.z; As[rr][c4 + 3] = va.w;
                            float4 vb = *(const float4*)&g_A[(c0 + rr) * LDA + j0 + c4];
                            Bs[rr][c4 + 0] = vb.x; Bs[rr][c4 + 1] = vb.y;
                            Bs[rr][c4 + 2] = vb.z; Bs[rr][c4 + 3] = vb.w;
                        }
                        __syncthreads();
                        int tx = tid & 15, ty = tid >> 4;
                        float acc[4][4] = {};
                        #pragma unroll
                        for (int kk = 0; kk < 64; kk++) {
                            float a[4], b[4];
                            #pragma unroll
                            for (int q = 0; q < 4; q++) { a[q] = As[ty * 4 + q][kk]; b[q] = Bs[tx * 4 + q][kk]; }
                            #pragma unroll
                            for (int qa = 0; qa < 4; qa++)
                                #pragma unroll
                                for (int qb = 0; qb < 4; qb++)
                                    acc[qa][qb] += a[qa] * b[qb];
                        }
                        #pragma unroll
                        for (int qa = 0; qa < 4; qa++) {
                            int i = r0 + ty * 4 + qa;
                            if (i <= Q) {
                                #pragma unroll
                                for (int qb = 0; qb < 4; qb++)
                                    g_A[i * LDA + c0 + tx * 4 + qb] -= acc[qa][qb];
                            }
                        }
                        __syncthreads();
                    }
                }
            }
        }
        grid_barrier();
    }

    // ---------- phase 5: final reduction (block 0) ----------
    if (bid == 0) {
        double* red = (double*)shraw;          // 256 doubles, aliases shA region
        double t = 0.0;
        for (int j = tid; j < Q; j += NTHR) {
            float w = g_A[Q * LDA + j];
            t += (double)w * (double)w;
        }
        red[tid] = t;
        __syncthreads();
        for (int s = 128; s > 0; s >>= 1) {
            if (tid < s) red[tid] += red[tid + s];
            __syncthreads();
        }
        if (tid == 0) {
            double tt  = red[0];
            double se  = (double)(*sig2e_p);
            double inv = 1.0 / se;
            double quad    = inv * g_sumrr - inv * inv * (g_uDu - tt);
            double logdetV = ((double)NTOT - (double)Q) * log(se) + 2.0 * g_logdet;
            const double LOG2PI = 1.8378770664093454835606594728112;
            out[0] = (float)(0.5 * (double)NTOT * LOG2PI + 0.5 * logdetV + 0.5 * quad);
        }
    }
}

extern "C" void kernel_launch(void* const* d_in, const int* in_sizes, int n_in,
                              void* d_out, int out_size) {
    const float* y_true = (const float*)d_in[0];
    const float* y_pred = (const float*)d_in[1];
    const int*   Z_idx  = (const int*)d_in[2];
    const float* dist   = (const float*)d_in[3];
    const float* sig2e  = (const float*)d_in[4];
    const float* sig2bs = (const float*)d_in[5];
    float* out = (float*)d_out;

    mega_kernel<<<NBLK, NTHR>>>(y_true, y_pred, Z_idx, dist, sig2e, sig2bs, out);
}

// round 6
// speedup vs baseline: 4.3396x; 1.6396x over previous
#include <cuda_runtime.h>
#include <cuda_bf16.h>
#include <math.h>

#define NTOT 4096
#define Q    1024
#define LDA  1024
#define NB   64
#define NBLK 128
#define NTHR 256

#define BAR96() asm volatile("bar.sync 1, 96;" ::: "memory")

// A is (Q+1) x Q: rows 0..1023 = S (then trailing rows become TRSM'd L rows),
// row 1024 = border vector v (becomes w = L^-1 v)
__device__ __align__(128) float g_A[(Q + 1) * LDA];
__device__ float  g_u[Q];
__device__ int    g_cnt[Q];
__device__ double g_sumrr;
__device__ double g_uDu;
__device__ double g_logdet;
__device__ unsigned g_barGen = 0;
__device__ unsigned g_barCnt = 0;

__device__ __forceinline__ void grid_barrier() {
    __threadfence();
    __syncthreads();
    if (threadIdx.x == 0) {
        unsigned gen = *(volatile unsigned*)&g_barGen;
        if (atomicAdd(&g_barCnt, 1u) == NBLK - 1u) {
            g_barCnt = 0;
            __threadfence();
            *(volatile unsigned*)&g_barGen = gen + 1u;
        } else {
            while (*(volatile unsigned*)&g_barGen == gen) { __nanosleep(64); }
        }
    }
    __syncthreads();
    __threadfence();
}

__global__ void __launch_bounds__(NTHR, 1)
mega_kernel(const float* __restrict__ yt,
            const float* __restrict__ yp,
            const int*   __restrict__ Z,
            const float* __restrict__ dist,
            const float* __restrict__ sig2e_p,
            const float* __restrict__ sig2bs,
            float* __restrict__ out)
{
    __shared__ __align__(16) float shA[64][65];
    __shared__ __align__(16) float shB[64][65];
    __shared__ float  shcol[2][64];
    __shared__ float  shInv[2];
    __shared__ float  shDiag[64];
    __shared__ double shLg[2];
    __shared__ float  shRed[NTHR];
    __shared__ double shRedD[NTHR];

    const int bid  = blockIdx.x;
    const int tid  = threadIdx.x;
    const int lane = tid & 31;

    // ---------------- phase 0: init ----------------
    {
        int i = bid * NTHR + tid;
        if (i < Q) { g_u[i] = 0.f; g_cnt[i] = 0; }
        if (bid == 0 && tid == 0) { g_sumrr = 0.0; g_uDu = 0.0; g_logdet = 0.0; }
    }
    grid_barrier();

    // ---------------- phase 1: scatter (Z_idx arrives as int32) ----------------
    {
        int gi = bid * NTHR + tid;
        float r2 = 0.f;
        if (gi < NTOT) {
            float r = yt[gi] - yp[gi];
            int q = Z[gi] & (Q - 1);
            atomicAdd(&g_u[q], r);
            atomicAdd(&g_cnt[q], 1);
            r2 = r * r;
        }
        #pragma unroll
        for (int o = 16; o > 0; o >>= 1) r2 += __shfl_down_sync(0xffffffffu, r2, o);
        if (lane == 0 && (gi - lane) < NTOT) atomicAdd(&g_sumrr, (double)r2);
    }
    grid_barrier();

    // ---------------- phase 2: build S + border v + uDu (8 rows / block) -------
    {
        float s0   = sig2bs[0];
        float cexp = -0.5f / sig2bs[1];
        float se   = *sig2e_p;
        int4  c4 = *(const int4*)&g_cnt[tid * 4];
        float sw0 = sqrtf((float)c4.x), sw1 = sqrtf((float)c4.y);
        float sw2 = sqrtf((float)c4.z), sw3 = sqrtf((float)c4.w);
        float4 u4 = *(const float4*)&g_u[tid * 4];
        double uDu_loc = 0.0;
        float4 dv[8];
        #pragma unroll
        for (int ii = 0; ii < 8; ii++)
            dv[ii] = ((const float4*)(dist + (bid * 8 + ii) * Q))[tid];
        #pragma unroll
        for (int ii = 0; ii < 8; ii++) {
            int i = bid * 8 + ii;
            float swi = sqrtf((float)g_cnt[i]);
            float e0 = s0 * __expf(cexp * dv[ii].x);
            float e1 = s0 * __expf(cexp * dv[ii].y);
            float e2 = s0 * __expf(cexp * dv[ii].z);
            float e3 = s0 * __expf(cexp * dv[ii].w);
            float partial = e0 * u4.x + e1 * u4.y + e2 * u4.z + e3 * u4.w;
            float4 o;
            o.x = swi * sw0 * e0; o.y = swi * sw1 * e1;
            o.z = swi * sw2 * e2; o.w = swi * sw3 * e3;
            if ((i >> 2) == tid) {
                // (bid*8+ii) & 3 == ii & 3 (compile-time after unroll)
                const int comp = ii & 3;
                if (comp == 0) o.x += se;
                else if (comp == 1) o.y += se;
                else if (comp == 2) o.z += se;
                else o.w += se;
            }
            ((float4*)&g_A[i * LDA])[tid] = o;
            shRed[tid] = partial;
            __syncthreads();
            for (int s = 128; s > 0; s >>= 1) {
                if (tid < s) shRed[tid] += shRed[tid + s];
                __syncthreads();
            }
            if (tid == 0) {
                float dot = shRed[0];
                g_A[Q * LDA + i] = swi * dot;      // border row v_i
                uDu_loc += (double)(g_u[i] * dot);
            }
            __syncthreads();
        }
        if (tid == 0) atomicAdd(&g_uDu, uDu_loc);
    }
    grid_barrier();

    // ---------------- phase 3: blocked bordered Cholesky ----------------
    for (int p = 0; p < Q / NB; p++) {
        const int j0 = p * NB;
        const int jb = j0 + NB;
        const int nrows = Q + 1 - jb;          // trailing rows incl. border

        // ---- phase A: redundant diag factor + fused register TRSM ----
        // threads 0..63: diag rows (register-resident). threads 64..95: this
        // block's 32 trailing rows, carried through the same column recurrence.
        const bool participate = (bid == 0) || (bid * 32 < nrows);
        if (participate && tid < 96) {
            int  myrow;
            bool valid;
            if (tid < 64) { myrow = j0 + tid; valid = true; }
            else {
                int i = jb + bid * 32 + (tid - 64);
                valid = (i <= Q);
                myrow = valid ? i : 0;
            }
            float a[64];
            if (valid) {
                const float4* src = (const float4*)&g_A[myrow * LDA + j0];
                #pragma unroll
                for (int t = 0; t < 16; t++) {
                    float4 v = src[t];
                    a[4*t] = v.x; a[4*t+1] = v.y; a[4*t+2] = v.z; a[4*t+3] = v.w;
                }
            } else {
                #pragma unroll
                for (int k = 0; k < 64; k++) a[k] = 0.f;
            }
            #pragma unroll
            for (int j = 0; j < 64; j++) {
                if (tid < 64) shcol[j & 1][tid] = a[j];       // publish col j
                if (tid == j) shInv[j & 1] = __fdividef(1.0f, a[j]);
                BAR96();
                float m = a[j] * shInv[j & 1];
                #pragma unroll
                for (int k = j + 1; k < 64; k++)
                    a[k] -= m * shcol[j & 1][k];
            }
            double lg = 0.0;
            if (tid < 64) {
                shDiag[tid] = rsqrtf(a[tid]);                 // 1/d_c
                if (bid == 0) lg = 0.5 * (double)logf(a[tid]); // 0.5*log(d^2)
            }
            #pragma unroll
            for (int o = 16; o > 0; o >>= 1) lg += __shfl_down_sync(0xffffffffu, lg, o);
            if (tid == 0)  shLg[0] = lg;
            if (tid == 32) shLg[1] = lg;
            BAR96();
            if (bid == 0 && tid == 0) g_logdet += shLg[0] + shLg[1];
            if (tid >= 64 && valid) {
                // TRSM'd row: x_c = a_c * (1/d_c)
                float4* dst = (float4*)&g_A[myrow * LDA + j0];
                #pragma unroll
                for (int t = 0; t < 16; t++) {
                    float4 v;
                    v.x = a[4*t]   * shDiag[4*t];
                    v.y = a[4*t+1] * shDiag[4*t+1];
                    v.z = a[4*t+2] * shDiag[4*t+2];
                    v.w = a[4*t+3] * shDiag[4*t+3];
                    dst[t] = v;
                }
            }
        }
        grid_barrier();

        // ---- phase B: SYRK trailing update (64x64 tiles, lower-tri only) ----
        {
            int colt = (Q - jb) >> 6;
            if (colt > 0) {
                int rowt = (nrows + 63) >> 6;
                int ntile = rowt * colt;
                for (int t = bid; t < ntile; t += NBLK) {
                    int ry = t / colt, cx = t - ry * colt;
                    int r0 = jb + ry * 64, c0 = jb + cx * 64;
                    if (c0 <= r0) {
                        for (int idx = tid; idx < 64 * 16; idx += NTHR) {
                            int rr = idx >> 4, c4 = (idx & 15) * 4;
                            int gi = r0 + rr;
                            float4 va = (gi <= Q) ? *(const float4*)&g_A[gi * LDA + j0 + c4]
                                                  : make_float4(0.f, 0.f, 0.f, 0.f);
                            shA[rr][c4 + 0] = va.x; shA[rr][c4 + 1] = va.y;
                            shA[rr][c4 + 2] = va.z; shA[rr][c4 + 3] = va.w;
                            float4 vb = *(const float4*)&g_A[(c0 + rr) * LDA + j0 + c4];
                            shB[rr][c4 + 0] = vb.x; shB[rr][c4 + 1] = vb.y;
                            shB[rr][c4 + 2] = vb.z; shB[rr][c4 + 3] = vb.w;
                        }
                        __syncthreads();
                        int tx = tid & 15, ty = tid >> 4;
                        float acc[4][4] = {};
                        #pragma unroll
                        for (int kk = 0; kk < 64; kk++) {
                            float av[4], bv[4];
                            #pragma unroll
                            for (int qq = 0; qq < 4; qq++) {
                                av[qq] = shA[ty * 4 + qq][kk];
                                bv[qq] = shB[tx * 4 + qq][kk];
                            }
                            #pragma unroll
                            for (int qa = 0; qa < 4; qa++)
                                #pragma unroll
                                for (int qb = 0; qb < 4; qb++)
                                    acc[qa][qb] += av[qa] * bv[qb];
                        }
                        #pragma unroll
                        for (int qa = 0; qa < 4; qa++) {
                            int i = r0 + ty * 4 + qa;
                            if (i <= Q) {
                                #pragma unroll
                                for (int qb = 0; qb < 4; qb++)
                                    g_A[i * LDA + c0 + tx * 4 + qb] -= acc[qa][qb];
                            }
                        }
                        __syncthreads();
                    }
                }
            }
        }
        grid_barrier();
    }

    // ---------------- phase 4: final reduction (block 0) ----------------
    if (bid == 0) {
        double t = 0.0;
        for (int j = tid; j < Q; j += NTHR) {
            float w = g_A[Q * LDA + j];
            t += (double)w * (double)w;
        }
        shRedD[tid] = t;
        __syncthreads();
        for (int s = 128; s > 0; s >>= 1) {
            if (tid < s) shRedD[tid] += shRedD[tid + s];
            __syncthreads();
        }
        if (tid == 0) {
            double tt  = shRedD[0];
            double se  = (double)(*sig2e_p);
            double inv = 1.0 / se;
            double quad    = inv * g_sumrr - inv * inv * (g_uDu - tt);
            double logdetV = ((double)NTOT - (double)Q) * log(se) + 2.0 * g_logdet;
            const double LOG2PI = 1.8378770664093454835606594728112;
            out[0] = (float)(0.5 * (double)NTOT * LOG2PI + 0.5 * logdetV + 0.5 * quad);
        }
    }
}

extern "C" void kernel_launch(void* const* d_in, const int* in_sizes, int n_in,
                              void* d_out, int out_size) {
    const float* y_true = (const float*)d_in[0];
    const float* y_pred = (const float*)d_in[1];
    const int*   Z_idx  = (const int*)d_in[2];
    const float* dist   = (const float*)d_in[3];
    const float* sig2e  = (const float*)d_in[4];
    const float* sig2bs = (const float*)d_in[5];
    float* out = (float*)d_out;

    mega_kernel<<<NBLK, NTHR>>>(y_true, y_pred, Z_idx, dist, sig2e, sig2bs, out);
}

// round 8
// speedup vs baseline: 6.0670x; 1.3981x over previous
#include <cuda_runtime.h>
#include <cuda_bf16.h>
#include <math.h>

#define NTOT 4096
#define Q    1024
#define LDA  1024
#define NB   64
#define NBLK 128
#define NTHR 256

#define BAR192() asm volatile("bar.sync 1, 192;" ::: "memory")

// A is (Q+1) x Q: rows 0..1023 = S (trailing rows become TRSM'd L rows),
// row 1024 = border vector v (becomes w = L^-1 v)
__device__ __align__(128) float g_A[(Q + 1) * LDA];
__device__ float  g_u[Q];
__device__ int    g_cnt[Q];
__device__ double g_sumrr;
__device__ double g_uDu;
__device__ double g_logdet;
__device__ unsigned g_barGen = 0;
__device__ unsigned g_barCnt = 0;

__device__ __forceinline__ void grid_barrier() {
    __threadfence();
    __syncthreads();
    if (threadIdx.x == 0) {
        unsigned gen = *(volatile unsigned*)&g_barGen;
        if (atomicAdd(&g_barCnt, 1u) == NBLK - 1u) {
            g_barCnt = 0;
            __threadfence();
            *(volatile unsigned*)&g_barGen = gen + 1u;
        } else {
            while (*(volatile unsigned*)&g_barGen == gen) { __nanosleep(32); }
        }
    }
    __syncthreads();
    __threadfence();
}

__global__ void __launch_bounds__(NTHR, 1)
mega_kernel(const float* __restrict__ yt,
            const float* __restrict__ yp,
            const int*   __restrict__ Z,
            const float* __restrict__ dist,
            const float* __restrict__ sig2e_p,
            const float* __restrict__ sig2bs,
            float* __restrict__ out)
{
    __shared__ __align__(16) float shA[64][65];
    __shared__ __align__(16) float shB[64][65];
    __shared__ float  shcol[2][96];
    __shared__ float  shInv[2];
    __shared__ float  shD2[64];
    __shared__ float  shDinv[64];
    __shared__ double shLg[2];
    __shared__ float  shRed[NTHR];
    __shared__ double shRedD[NTHR];

    const int bid  = blockIdx.x;
    const int tid  = threadIdx.x;
    const int lane = tid & 31;

    // ---------------- phase 0: init ----------------
    {
        int i = bid * NTHR + tid;
        if (i < Q) { g_u[i] = 0.f; g_cnt[i] = 0; }
        if (bid == 0 && tid == 0) { g_sumrr = 0.0; g_uDu = 0.0; g_logdet = 0.0; }
    }
    grid_barrier();

    // ---------------- phase 1: scatter (Z_idx arrives as int32) ----------------
    {
        int gi = bid * NTHR + tid;
        float r2 = 0.f;
        if (gi < NTOT) {
            float r = yt[gi] - yp[gi];
            int q = Z[gi] & (Q - 1);
            atomicAdd(&g_u[q], r);
            atomicAdd(&g_cnt[q], 1);
            r2 = r * r;
        }
        #pragma unroll
        for (int o = 16; o > 0; o >>= 1) r2 += __shfl_down_sync(0xffffffffu, r2, o);
        if (lane == 0 && (gi - lane) < NTOT) atomicAdd(&g_sumrr, (double)r2);
    }
    grid_barrier();

    // ---------------- phase 2: build S + border v + uDu (8 rows / block) -------
    {
        float s0   = sig2bs[0];
        float cexp = -0.5f / sig2bs[1];
        float se   = *sig2e_p;
        int4  c4 = *(const int4*)&g_cnt[tid * 4];
        float sw0 = sqrtf((float)c4.x), sw1 = sqrtf((float)c4.y);
        float sw2 = sqrtf((float)c4.z), sw3 = sqrtf((float)c4.w);
        float4 u4 = *(const float4*)&g_u[tid * 4];
        double uDu_loc = 0.0;
        float4 dv[8];
        #pragma unroll
        for (int ii = 0; ii < 8; ii++)
            dv[ii] = ((const float4*)(dist + (bid * 8 + ii) * Q))[tid];
        #pragma unroll
        for (int ii = 0; ii < 8; ii++) {
            int i = bid * 8 + ii;
            float swi = sqrtf((float)g_cnt[i]);
            float e0 = s0 * __expf(cexp * dv[ii].x);
            float e1 = s0 * __expf(cexp * dv[ii].y);
            float e2 = s0 * __expf(cexp * dv[ii].z);
            float e3 = s0 * __expf(cexp * dv[ii].w);
            float partial = e0 * u4.x + e1 * u4.y + e2 * u4.z + e3 * u4.w;
            float4 o;
            o.x = swi * sw0 * e0; o.y = swi * sw1 * e1;
            o.z = swi * sw2 * e2; o.w = swi * sw3 * e3;
            if ((i >> 2) == tid) {
                const int comp = ii & 3;
                if (comp == 0) o.x += se;
                else if (comp == 1) o.y += se;
                else if (comp == 2) o.z += se;
                else o.w += se;
            }
            ((float4*)&g_A[i * LDA])[tid] = o;
            shRed[tid] = partial;
            __syncthreads();
            for (int s = 128; s > 0; s >>= 1) {
                if (tid < s) shRed[tid] += shRed[tid + s];
                __syncthreads();
            }
            if (tid == 0) {
                float dot = shRed[0];
                g_A[Q * LDA + i] = swi * dot;      // border row v_i
                uDu_loc += (double)(g_u[i] * dot);
            }
            __syncthreads();
        }
        if (tid == 0) atomicAdd(&g_uDu, uDu_loc);
    }
    grid_barrier();

    // ---------------- phase 3: blocked bordered Cholesky ----------------
    for (int p = 0; p < Q / NB; p++) {
        const int j0 = p * NB;
        const int jb = j0 + NB;
        const int nrows = Q + 1 - jb;          // trailing rows incl. border

        // ---- phase A: redundant diag factor + fused TRSM, parity-split,
        //      software-pipelined (1 bar/column, divide off-chain) ----
        const bool participate = (bid == 0) || (bid * 32 < nrows);
        if (participate && tid < 192) {
            const int par  = tid & 1;
            const int rIdx = tid >> 1;          // 0..63 diag, 64..95 trailing
            const bool isDiag = (tid < 128);
            int  myrow;
            bool valid;
            if (isDiag) { myrow = j0 + rIdx; valid = true; }
            else        { myrow = jb + bid * 32 + (rIdx - 64); valid = (myrow <= Q); }

            float a[32];                        // entries k = 2*kl + par
            if (valid) {
                const float4* src = (const float4*)&g_A[myrow * LDA + j0];
                #pragma unroll
                for (int t = 0; t < 16; t++) {
                    float4 v = src[t];
                    a[2*t]   = par ? v.y : v.x;
                    a[2*t+1] = par ? v.w : v.z;
                }
            } else {
                #pragma unroll
                for (int t = 0; t < 32; t++) a[t] = 0.f;
            }

            float d2 = 1.0f;
            if (par == 0) shcol[0][rIdx] = a[0];
            if (tid == 0) { d2 = a[0]; shInv[0] = __fdividef(1.0f, a[0]); }
            BAR192();

            #pragma unroll
            for (int j = 0; j < 63; j++) {
                const int cb = j & 1, nb2 = cb ^ 1;
                const int c  = (j + 1) & 1;     // parity owning entry j+1
                float m = shcol[cb][rIdx] * shInv[cb];
                // head: entry j+1 -> publish col j+1 (+ its reciprocal)
                if (par == c) {
                    const int klh = (j + 1) >> 1;
                    float v = a[klh] - m * shcol[cb][j + 1];
                    a[klh] = v;
                    if (tid == 2 * (j + 1) + c) {   // diag owner of row j+1
                        d2 = v;
                        shInv[nb2] = __fdividef(1.0f, v);
                    }
                    shcol[nb2][rIdx] = v;
                }
                // tail: entries k >= j+2 (overlaps the barrier wait)
                #pragma unroll
                for (int kl = (j + 2) >> 1; kl < 32; kl++) {
                    if (2 * kl + par >= j + 2)
                        a[kl] -= m * shcol[cb][2 * kl + par];
                }
                BAR192();
            }

            // publish diagonal d^2 and 1/d
            if (isDiag && par == (rIdx & 1)) {
                shD2[rIdx]   = d2;
                shDinv[rIdx] = rsqrtf(d2);
            }
            BAR192();

            // trailing rows: scale by 1/d and store TRSM'd row
            if (!isDiag && valid) {
                #pragma unroll
                for (int t = 0; t < 32; t++)
                    g_A[myrow * LDA + j0 + 2 * t + par] = a[t] * shDinv[2 * t + par];
            }
            // logdet contribution (block 0 only)
            if (bid == 0) {
                float lg = 0.f;
                if (tid < 64) {
                    lg = 0.5f * logf(shD2[tid]);
                    #pragma unroll
                    for (int o = 16; o > 0; o >>= 1)
                        lg += __shfl_down_sync(0xffffffffu, lg, o);
                    if (tid == 0)  shLg[0] = (double)lg;
                    if (tid == 32) shLg[1] = (double)lg;
                }
                BAR192();
                if (tid == 0) g_logdet += shLg[0] + shLg[1];
            }
        }
        grid_barrier();

        // ---- phase B: SYRK trailing update (64x64 tiles, lower-tri only) ----
        {
            int colt = (Q - jb) >> 6;
            if (colt > 0) {
                int rowt = (nrows + 63) >> 6;
                int ntile = rowt * colt;
                for (int t = bid; t < ntile; t += NBLK) {
                    int ry = t / colt, cx = t - ry * colt;
                    int r0 = jb + ry * 64, c0 = jb + cx * 64;
                    if (c0 <= r0) {
                        for (int idx = tid; idx < 64 * 16; idx += NTHR) {
                            int rr = idx >> 4, c4i = (idx & 15) * 4;
                            int gi = r0 + rr;
                            float4 va = (gi <= Q) ? *(const float4*)&g_A[gi * LDA + j0 + c4i]
                                                  : make_float4(0.f, 0.f, 0.f, 0.f);
                            shA[rr][c4i + 0] = va.x; shA[rr][c4i + 1] = va.y;
                            shA[rr][c4i + 2] = va.z; shA[rr][c4i + 3] = va.w;
                            float4 vb = *(const float4*)&g_A[(c0 + rr) * LDA + j0 + c4i];
                            shB[rr][c4i + 0] = vb.x; shB[rr][c4i + 1] = vb.y;
                            shB[rr][c4i + 2] = vb.z; shB[rr][c4i + 3] = vb.w;
                        }
                        __syncthreads();
                        int tx = tid & 15, ty = tid >> 4;
                        float acc[4][4] = {};
                        #pragma unroll
                        for (int kk = 0; kk < 64; kk++) {
                            float av[4], bv[4];
                            #pragma unroll
                            for (int qq = 0; qq < 4; qq++) {
                                av[qq] = shA[ty * 4 + qq][kk];
                                bv[qq] = shB[tx * 4 + qq][kk];
                            }
                            #pragma unroll
                            for (int qa = 0; qa < 4; qa++)
                                #pragma unroll
                                for (int qb = 0; qb < 4; qb++)
                                    acc[qa][qb] += av[qa] * bv[qb];
                        }
                        #pragma unroll
                        for (int qa = 0; qa < 4; qa++) {
                            int i = r0 + ty * 4 + qa;
                            if (i <= Q) {
                                #pragma unroll
                                for (int qb = 0; qb < 4; qb++)
                                    g_A[i * LDA + c0 + tx * 4 + qb] -= acc[qa][qb];
                            }
                        }
                        __syncthreads();
                    }
                }
            }
        }
        grid_barrier();
    }

    // ---------------- phase 4: final reduction (block 0) ----------------
    if (bid == 0) {
        double t = 0.0;
        for (int j = tid; j < Q; j += NTHR) {
            float w = g_A[Q * LDA + j];
            t += (double)w * (double)w;
        }
        shRedD[tid] = t;
        __syncthreads();
        for (int s = 128; s > 0; s >>= 1) {
            if (tid < s) shRedD[tid] += shRedD[tid + s];
            __syncthreads();
        }
        if (tid == 0) {
            double tt  = shRedD[0];
            double se  = (double)(*sig2e_p);
            double inv = 1.0 / se;
            double quad    = inv * g_sumrr - inv * inv * (g_uDu - tt);
            double logdetV = ((double)NTOT - (double)Q) * log(se) + 2.0 * g_logdet;
            const double LOG2PI = 1.8378770664093454835606594728112;
            out[0] = (float)(0.5 * (double)NTOT * LOG2PI + 0.5 * logdetV + 0.5 * quad);
        }
    }
}

extern "C" void kernel_launch(void* const* d_in, const int* in_sizes, int n_in,
                              void* d_out, int out_size) {
    const float* y_true = (const float*)d_in[0];
    const float* y_pred = (const float*)d_in[1];
    const int*   Z_idx  = (const int*)d_in[2];
    const float* dist   = (const float*)d_in[3];
    const float* sig2e  = (const float*)d_in[4];
    const float* sig2bs = (const float*)d_in[5];
    float* out = (float*)d_out;

    mega_kernel<<<NBLK, NTHR>>>(y_true, y_pred, Z_idx, dist, sig2e, sig2bs, out);
}